// round 15
// baseline (speedup 1.0000x reference)
#include <cuda_runtime.h>
#include <cstdint>

// HIRNN (GR4J-style) forward, R14: R13 step + 2 warps per SMSP.
//
// R5/R13 showed neither op-count nor chain-depth moves the needle: a lone
// warp issues ~30 instr per ~90 cycles (static-schedule stall exposure).
// Fix is occupancy at the SMSP level: 256-thread blocks put warps {w, w+4}
// on the same SMSP (wid%4), so the hardware arbiter interleaves two
// independent rows' chains -- the thing R6 proved ptxas won't do inside one
// thread. 16 blocks x 256 threads = same 128 warps, now 2/SMSP on 16 SMs.
// RF: 142 regs x 64 thr/SMSP = 9088 < 16384 -- no pressure.
//
// Step identities (exact away from <=1e-6 heaviside ties):
//  - heaviside select pairs == min/max
//  - s >= 0 provable -> max(s,0) dropped; u' = min(s_cap, min(s_inr,1))
//    with s_inr off-chain (min hoisted through fma, fi >= 0)
//  - GW >= 0 by induction  =>  BAS = RecK*GW,  GW' = (1-RecK)*GW + RECn
//  - ov = max(s-1,0) == s - min(s,1);  clip(+-1e5) provably inactive
//  - state normalized u = SMS/SMSC in [0,1]
// Q[t] (t>=1) uses the pre-step state at t (in-loop); Q[0] uses the FINAL
// state (roll shift=1), recomputed after the loop.

__device__ __forceinline__ float ex2f(float x) {
    float y;
    asm("ex2.approx.f32 %0, %1;" : "=f"(y) : "f"(x));
    return y;
}

struct Params {
    float INSC, SMSC, SUB, CRAK, RecK, alpha, ivS, ck2, lC, nSUB, nCRbi;
};

__device__ __forceinline__ float stepq(float Prec, float PET,
                                       float& u, float& GW, const Params& p)
{
    float INTm = fminf(PET, Prec);            // alu
    float INT  = fminf(p.INSC, INTm);         // alu
    float INR  = Prec - INT;                  // fma
    float POT  = PET - INT;                   // fma

    // ---- loop-carried chain ----
    float arg = fmaf(p.ck2, u, p.lC);         // fma   (needs u)
    float cap = ex2f(arg);                    // mufu : COEFF*exp(-SQ*u)

    // ---- off-chain, inside the MUFU shadow ----
    float t10   = u * 10.0f;                  // fma
    float m     = fminf(t10, POT);            // alu : ETS
    float base  = fmaf(-p.ivS, m, u);         // fma : u - ETS/SMSC  (>= 0)
    float a     = fmaf(p.nSUB,  u, 1.0f);     // fma : 1 - SUB*u
    float bi    = fmaf(p.nCRbi, u, p.ivS);    // fma : (1 - CRAK*u)/SMSC
    float fi    = a * bi;                     // fma  (>= 0)
    float s_inr = fmaf(INR, fi, base);        // fma : s if INR-limited
    float t2    = fminf(s_inr, 1.0f);         // alu

    // ---- chain tail ----
    float s_cap = fmaf(cap, fi, base);        // fma : s if cap-limited
    float u_n   = fminf(s_cap, t2);           // alu : next u = min(s,1), s>=0

    // ---- off-chain tail: recharge / groundwater / discharge ----
    float s    = fminf(s_cap, s_inr);         // alu : true pre-clamp s
    float ov   = s - u_n;                     // fma : == max(s-1,0)
    float RMO  = fminf(cap, INR);             // alu
    float w    = u * RMO;                     // fma
    float cw   = p.CRAK * w;                  // fma
    float REC  = cw * a;                      // fma
    float RECn = fmaf(p.SMSC, ov, REC);       // fma
    float dq   = INR - RMO;                   // fma
    float t1   = fmaf(p.RecK, GW, dq);        // fma : IRUN + BAS
    float q    = fmaf(p.SUB,  w,  t1);        // fma : + SRUN

    GW = fmaf(p.alpha, GW, RECn);             // fma : (1-RecK)*GW + RECn
    u  = u_n;
    return q;
}

template <int T>
__global__ __launch_bounds__(256, 1)
void hirnn_kernel(const float* __restrict__ in,
                  const float* __restrict__ pINSC,
                  const float* __restrict__ pCOEFF,
                  const float* __restrict__ pSQ,
                  const float* __restrict__ pSMSC,
                  const float* __restrict__ pSUB,
                  const float* __restrict__ pCRAK,
                  const float* __restrict__ pRecK,
                  float* __restrict__ out, int B)
{
    int bidx = blockIdx.x * 256 + threadIdx.x;
    if (bidx >= B) return;

    Params p;
    p.INSC   = fminf(fmaxf(pINSC[0]  * 5.f,   0.5f),   5.f);
    float CO = fminf(fmaxf(pCOEFF[0] * 400.f, 50.f),   400.f);
    float SQ = fminf(fmaxf(pSQ[0]    * 6.f,   0.f),    6.f);
    p.SMSC   = fminf(fmaxf(pSMSC[0]  * 500.f, 50.f),   500.f);
    p.SUB    = fminf(fmaxf(pSUB[0],           0.f),    1.f);
    p.CRAK   = fminf(fmaxf(pCRAK[0],          0.f),    1.f);
    p.RecK   = fminf(fmaxf(pRecK[0]  * 0.3f,  0.003f), 0.3f);
    p.alpha  = 1.f - p.RecK;
    p.ivS    = 1.f / p.SMSC;
    p.ck2    = -SQ * 1.44269504088896340736f;   // -SQ*log2(e)
    p.lC     = __log2f(CO);
    p.nSUB   = -p.SUB;
    p.nCRbi  = -p.CRAK * p.ivS;

    const float4* row  = reinterpret_cast<const float4*>(in + (size_t)bidx * T * 2);
    float4*       orow = reinterpret_cast<float4*>(out + (size_t)bidx * T);

    constexpr int NBODY = T / 16;   // 64 bodies of 16 timesteps

    float4 buf[8];
    #pragma unroll
    for (int j = 0; j < 8; ++j) buf[j] = __ldg(&row[j]);

    float Prec0 = buf[0].x, PET0 = buf[0].y;
    float u = 0.f, GW = 0.f;

    for (int i = 0; i < NBODY; ++i) {
        // prefetch next body (last iter: reload body 0, discarded)
        int nb = (i + 1 < NBODY) ? (i + 1) * 8 : 0;
        float4 nxt[8];
        #pragma unroll
        for (int j = 0; j < 8; ++j) nxt[j] = __ldg(&row[nb + j]);

        // compute 16 steps from buf
        #pragma unroll
        for (int k = 0; k < 4; ++k) {
            float4 q;
            q.x = stepq(buf[2*k].x,   buf[2*k].y,   u, GW, p);
            q.y = stepq(buf[2*k].z,   buf[2*k].w,   u, GW, p);
            q.z = stepq(buf[2*k+1].x, buf[2*k+1].y, u, GW, p);
            q.w = stepq(buf[2*k+1].z, buf[2*k+1].w, u, GW, p);
            orow[i * 4 + k] = q;   // q.x at i==0,k==0 is a placeholder
        }

        #pragma unroll
        for (int j = 0; j < 8; ++j) buf[j] = nxt[j];
    }

    // Q[0]: roll(shift=1) puts the FINAL state at t=0.
    float u2 = u, g2 = GW;
    out[(size_t)bidx * T] = stepq(Prec0, PET0, u2, g2, p);
}

extern "C" void kernel_launch(void* const* d_in, const int* in_sizes, int n_in,
                              void* d_out, int out_size)
{
    const float* in    = (const float*)d_in[0];
    const float* INSC  = (const float*)d_in[1];
    const float* COEFF = (const float*)d_in[2];
    const float* SQ    = (const float*)d_in[3];
    const float* SMSC  = (const float*)d_in[4];
    const float* SUB   = (const float*)d_in[5];
    const float* CRAK  = (const float*)d_in[6];
    const float* RecK  = (const float*)d_in[7];
    float* out = (float*)d_out;

    constexpr int T = 1024;
    int B = out_size / T;
    int blocks = (B + 255) / 256;
    hirnn_kernel<T><<<blocks, 256>>>(in, INSC, COEFF, SQ, SMSC, SUB, CRAK, RecK,
                                     out, B);
}

// round 17
// speedup vs baseline: 1.6109x; 1.6109x over previous
#include <cuda_runtime.h>
#include <cstdint>

// HIRNN (GR4J-style) forward, R16: R13 math + MANUAL SOFTWARE PIPELINING.
// In iteration t: issue arg->ex2 for step t, then compute the FULL tail of
// step t-1 (q, REC, GW update) inside the MUFU shadow, then finish step t.
// Identical arithmetic to R13 (same instrs, reordered) -> bitwise-same output.
// Geometry: 128 blocks x 32 thr (R14 proved warps must stay spread: per-SM
// DRAM-MLP cap ~27GB/s makes any concentration memory-bound).
//
// Step identities (exact away from <=1e-6 heaviside ties):
//  - heaviside select pairs == min/max
//  - s >= 0 provable -> u' = min(s_cap, min(s_inr,1)), s_inr off-chain
//  - GW >= 0 by induction  =>  GW' = (1-RecK)*GW + RECn; BAS folded into q
//  - ov = max(s-1,0) == s - min(s,1);  clip(+-1e5) provably inactive
//  - state normalized u = SMS/SMSC in [0,1]
// Q[t] (t>=1) uses the pre-step state at t; Q[0] uses the FINAL state
// (roll shift=1), recomputed in the epilogue.

__device__ __forceinline__ float ex2f(float x) {
    float y;
    asm("ex2.approx.f32 %0, %1;" : "=f"(y) : "f"(x));
    return y;
}

struct Params {
    float INSC, SMSC, SUB, CRAK, RecK, alpha, ivS, ck2, lC, nSUB, nCRbi;
};

// Staged state of step t-1, consumed by its tail during iteration t.
struct Staged { float cap, s_cap, s_inr, u_old, a, INR; };

// Tail of the staged step: q + GW update. u_new = u entering iteration t
// (= post-step-(t-1) state), GW = GW entering step t-1 (updated in place).
__device__ __forceinline__ float tail_q(const Staged& st, float u_new,
                                        float& GW, const Params& p)
{
    float s    = fminf(st.s_cap, st.s_inr);   // true pre-clamp s
    float ov   = s - u_new;                   // == max(s-1,0)
    float RMO  = fminf(st.cap, st.INR);
    float w    = st.u_old * RMO;
    float cw   = p.CRAK * w;
    float REC  = cw * st.a;
    float RECn = fmaf(p.SMSC, ov, REC);
    float dq   = st.INR - RMO;
    float t1   = fmaf(p.RecK, GW, dq);        // IRUN + BAS
    float q    = fmaf(p.SUB, w, t1);          // + SRUN
    GW = fmaf(p.alpha, GW, RECn);             // (1-RecK)*GW + RECn
    return q;
}

// One pipelined step: start step t's chain, run step t-1's tail in the MUFU
// shadow, finish step t. Returns q_{t-1}.
__device__ __forceinline__ float pstep(float Prec, float PET,
                                       float& u, float& GW, Staged& st,
                                       const Params& p)
{
    // head: chain start for step t
    float arg = fmaf(p.ck2, u, p.lC);
    float cap = ex2f(arg);                    // MUFU in flight...

    // ...tail of step t-1 fills the shadow
    float qprev = tail_q(st, u, GW, p);

    // step-t off-chain
    float INTm = fminf(PET, Prec);
    float INT  = fminf(p.INSC, INTm);
    float INR  = Prec - INT;
    float POT  = PET - INT;
    float t10  = u * 10.0f;
    float m    = fminf(t10, POT);
    float base = fmaf(-p.ivS, m, u);          // u - ETS/SMSC (>= 0)
    float a    = fmaf(p.nSUB, u, 1.0f);       // 1 - SUB*u
    float bi   = fmaf(p.nCRbi, u, p.ivS);     // (1 - CRAK*u)/SMSC
    float fi   = a * bi;                      // >= 0
    float s_inr = fmaf(INR, fi, base);
    float t2   = fminf(s_inr, 1.0f);

    // consume cap; resolve
    float s_cap = fmaf(cap, fi, base);
    float u_n   = fminf(s_cap, t2);           // next u = min(s,1), s >= 0

    st.cap = cap; st.s_cap = s_cap; st.s_inr = s_inr;
    st.u_old = u; st.a = a; st.INR = INR;
    u = u_n;
    return qprev;
}

// 16 steps from a register buffer; q-stores are shifted by one step.
__device__ __forceinline__ void body16(const float4* buf, int base,
                                       float& u, float& GW, Staged& st,
                                       float4& qtmp, const Params& p,
                                       float4* orow)
{
    #pragma unroll
    for (int k = 0; k < 16; ++k) {
        float4 v = buf[k >> 1];
        float Pr = (k & 1) ? v.z : v.x;
        float Pe = (k & 1) ? v.w : v.y;
        float qv = pstep(Pr, Pe, u, GW, st, p);
        int j = (k + 3) & 3;                  // == (t-1) & 3
        if      (j == 0) qtmp.x = qv;
        else if (j == 1) qtmp.y = qv;
        else if (j == 2) qtmp.z = qv;
        else {
            qtmp.w = qv;
            int idx = (base + k - 1) >> 2;
            idx = idx < 0 ? 0 : idx;          // body0/k0: junk into group 0,
            orow[idx] = qtmp;                 // overwritten by k=4 (same thread)
        }
    }
}

template <int T>
__global__ __launch_bounds__(32, 1)
void hirnn_kernel(const float* __restrict__ in,
                  const float* __restrict__ pINSC,
                  const float* __restrict__ pCOEFF,
                  const float* __restrict__ pSQ,
                  const float* __restrict__ pSMSC,
                  const float* __restrict__ pSUB,
                  const float* __restrict__ pCRAK,
                  const float* __restrict__ pRecK,
                  float* __restrict__ out, int B)
{
    int bidx = blockIdx.x * 32 + threadIdx.x;
    if (bidx >= B) return;

    Params p;
    p.INSC   = fminf(fmaxf(pINSC[0]  * 5.f,   0.5f),   5.f);
    float CO = fminf(fmaxf(pCOEFF[0] * 400.f, 50.f),   400.f);
    float SQ = fminf(fmaxf(pSQ[0]    * 6.f,   0.f),    6.f);
    p.SMSC   = fminf(fmaxf(pSMSC[0]  * 500.f, 50.f),   500.f);
    p.SUB    = fminf(fmaxf(pSUB[0],           0.f),    1.f);
    p.CRAK   = fminf(fmaxf(pCRAK[0],          0.f),    1.f);
    p.RecK   = fminf(fmaxf(pRecK[0]  * 0.3f,  0.003f), 0.3f);
    p.alpha  = 1.f - p.RecK;
    p.ivS    = 1.f / p.SMSC;
    p.ck2    = -SQ * 1.44269504088896340736f;   // -SQ*log2(e)
    p.lC     = __log2f(CO);
    p.nSUB   = -p.SUB;
    p.nCRbi  = -p.CRAK * p.ivS;

    const float4* row  = reinterpret_cast<const float4*>(in + (size_t)bidx * T * 2);
    float4*       orow = reinterpret_cast<float4*>(out + (size_t)bidx * T);

    constexpr int NBODY = T / 16;   // 64 (even)

    float4 A[8], Bb[8];
    #pragma unroll
    for (int j = 0; j < 8; ++j) A[j] = __ldg(&row[j]);

    float Prec0 = A[0].x, PET0 = A[0].y;

    float u = 0.f, GW = 0.f;
    Staged st = {0.f, 0.f, 0.f, 0.f, 0.f, 0.f};  // zero tail for t = -1
    float4 qtmp = make_float4(0.f, 0.f, 0.f, 0.f);

    for (int i = 0; i < NBODY; i += 2) {
        // prefetch body i+1 (i+1 <= NBODY-1: always valid)
        #pragma unroll
        for (int j = 0; j < 8; ++j) Bb[j] = __ldg(&row[(i + 1) * 8 + j]);
        body16(A, i * 16, u, GW, st, qtmp, p, orow);

        // prefetch body i+2 (last pair: dummy reload of body 0)
        int j2 = (i + 2 < NBODY) ? i + 2 : 0;
        #pragma unroll
        for (int j = 0; j < 8; ++j) A[j] = __ldg(&row[j2 * 8 + j]);
        body16(Bb, (i + 1) * 16, u, GW, st, qtmp, p, orow);
    }

    // epilogue 1: tail of step T-1 -> q[T-1], store last group.
    float qlast = tail_q(st, u, GW, p);           // GW becomes GW_T
    qtmp.w = qlast;
    orow[(T - 1) >> 2] = qtmp;

    // epilogue 2: Q[0] = roll(shift=1) -> full step from FINAL state (u, GW).
    {
        float arg = fmaf(p.ck2, u, p.lC);
        float cap = ex2f(arg);
        float INTm = fminf(PET0, Prec0);
        float INT  = fminf(p.INSC, INTm);
        float INR  = Prec0 - INT;
        float POT  = PET0 - INT;
        float t10  = u * 10.0f;
        float m    = fminf(t10, POT);
        float base = fmaf(-p.ivS, m, u);
        float a    = fmaf(p.nSUB, u, 1.0f);
        float bi   = fmaf(p.nCRbi, u, p.ivS);
        float fi   = a * bi;
        float s_inr = fmaf(INR, fi, base);
        float t2   = fminf(s_inr, 1.0f);
        float s_cap = fmaf(cap, fi, base);
        float u_n   = fminf(s_cap, t2);
        Staged st2 = {cap, s_cap, s_inr, u, a, INR};
        float g2 = GW;
        float q0 = tail_q(st2, u_n, g2, p);
        out[(size_t)bidx * T] = q0;
    }
}

extern "C" void kernel_launch(void* const* d_in, const int* in_sizes, int n_in,
                              void* d_out, int out_size)
{
    const float* in    = (const float*)d_in[0];
    const float* INSC  = (const float*)d_in[1];
    const float* COEFF = (const float*)d_in[2];
    const float* SQ    = (const float*)d_in[3];
    const float* SMSC  = (const float*)d_in[4];
    const float* SUB   = (const float*)d_in[5];
    const float* CRAK  = (const float*)d_in[6];
    const float* RecK  = (const float*)d_in[7];
    float* out = (float*)d_out;

    constexpr int T = 1024;
    int B = out_size / T;
    int blocks = (B + 31) / 32;
    hirnn_kernel<T><<<blocks, 32>>>(in, INSC, COEFF, SQ, SMSC, SUB, CRAK, RecK,
                                    out, B);
}